// round 1
// baseline (speedup 1.0000x reference)
#include <cuda_runtime.h>
#include <cstdint>

#define N_USERS 100000
#define N_ITEMS 50000
#define N_NODESC 150000
#define NNZC 2400000
#define DIM 64
#define BATCHC 4096
#define HALFC 4800000u
#define NPAIR 75000
#define EPSC 0.1f
#define INV_TEMP 5.0f

// ---------------- static device scratch (allocation-free) ----------------
__device__ float g_ego [N_NODESC * DIM];
__device__ float g_bufA[N_NODESC * DIM];
__device__ float g_bufB[N_NODESC * DIM];
__device__ float g_sum [N_NODESC * DIM];
__device__ int2  g_cv[NNZC];            // (col, val bits) sorted by row
__device__ int   g_rowptr[N_NODESC + 1];
__device__ int   g_cursor[N_NODESC];
__device__ int   g_counts[N_NODESC];
__device__ int   g_blocksums[256];
__device__ int   g_flags[N_NODESC];     // users at [0,100000), items at [100000,150000)
__device__ int   g_uidx[BATCHC];
__device__ int   g_iidx[BATCHC];
__device__ int   g_ucnt;
__device__ int   g_icnt;
__device__ float g_V1u[BATCHC * DIM], g_V2u[BATCHC * DIM];
__device__ float g_V1i[BATCHC * DIM], g_V2i[BATCHC * DIM];
__device__ float g_posU[BATCHC], g_posI[BATCHC];
__device__ float g_S[2 * BATCHC];       // per-row sum(exp(logit-5)): users then items
__device__ float g_acc[8];              // 0 rec, 1 ssu, 2 ssp, 3 nceU, 4 nceI

// ---------------- threefry-2x32 (exact JAX schedule) ----------------
__host__ __device__ __forceinline__ unsigned rl32(unsigned x, int r) {
    return (x << r) | (x >> (32 - r));
}
__host__ __device__ __forceinline__ void tf2x32(unsigned k0, unsigned k1,
                                                unsigned x0, unsigned x1,
                                                unsigned& o0, unsigned& o1) {
    unsigned k2 = k0 ^ k1 ^ 0x1BD11BDAu;
    x0 += k0; x1 += k1;
#define TFR(r) { x0 += x1; x1 = rl32(x1, r); x1 ^= x0; }
    TFR(13) TFR(15) TFR(26) TFR(6)
    x0 += k1; x1 += k2 + 1u;
    TFR(17) TFR(29) TFR(16) TFR(24)
    x0 += k2; x1 += k0 + 2u;
    TFR(13) TFR(15) TFR(26) TFR(6)
    x0 += k0; x1 += k1 + 3u;
    TFR(17) TFR(29) TFR(16) TFR(24)
    x0 += k1; x1 += k2 + 4u;
    TFR(13) TFR(15) TFR(26) TFR(6)
    x0 += k2; x1 += k0 + 5u;
#undef TFR
    o0 = x0; o1 = x1;
}
__device__ __forceinline__ float u32_to_unit(unsigned b) {
    return __uint_as_float((b >> 9) | 0x3f800000u) - 1.0f;
}
__device__ __forceinline__ float wredsum(float v) {
#pragma unroll
    for (int o = 16; o; o >>= 1) v += __shfl_xor_sync(0xffffffffu, v, o);
    return v;
}
__device__ __forceinline__ float* bufsel(int id) {
    switch (id) {
        case 0: return g_ego;
        case 1: return g_bufA;
        case 2: return g_bufB;
        default: return g_sum;
    }
}

// ---------------- setup kernels ----------------
__global__ void k_zero() {
    int i = blockIdx.x * blockDim.x + threadIdx.x;
    if (i < N_NODESC) { g_flags[i] = 0; g_counts[i] = 0; }
    if (i < 2 * BATCHC) g_S[i] = 0.f;
    if (i < 8) g_acc[i] = 0.f;
    if (i == 0) { g_ucnt = 0; g_icnt = 0; }
}
__global__ void k_hist(const int* __restrict__ rows) {
    int i = blockIdx.x * blockDim.x + threadIdx.x;
    if (i < NNZC) atomicAdd(&g_counts[rows[i]], 1);
}
__global__ void k_scan1() {
    __shared__ int sh[1024];
    int g = blockIdx.x * 1024 + threadIdx.x;
    int v = (g < N_NODESC) ? g_counts[g] : 0;
    sh[threadIdx.x] = v;
    __syncthreads();
    for (int off = 1; off < 1024; off <<= 1) {
        int t = (threadIdx.x >= off) ? sh[threadIdx.x - off] : 0;
        __syncthreads();
        sh[threadIdx.x] += t;
        __syncthreads();
    }
    if (g < N_NODESC) g_rowptr[g] = sh[threadIdx.x] - v;   // exclusive within block
    if (threadIdx.x == 1023) g_blocksums[blockIdx.x] = sh[1023];
}
__global__ void k_scan2(int nblocks) {
    if (threadIdx.x == 0) {
        int acc = 0;
        for (int b = 0; b < nblocks; b++) { int t = g_blocksums[b]; g_blocksums[b] = acc; acc += t; }
        g_rowptr[N_NODESC] = acc;
    }
}
__global__ void k_scan3() {
    int g = blockIdx.x * blockDim.x + threadIdx.x;
    if (g < N_NODESC) {
        int v = g_rowptr[g] + g_blocksums[g >> 10];
        g_rowptr[g] = v;
        g_cursor[g] = v;
    }
}
__global__ void k_fill(const int* __restrict__ rows, const int* __restrict__ cols,
                       const float* __restrict__ vals) {
    int i = blockIdx.x * blockDim.x + threadIdx.x;
    if (i < NNZC) {
        int p = atomicAdd(&g_cursor[rows[i]], 1);
        g_cv[p] = make_int2(cols[i], __float_as_int(vals[i]));
    }
}
__global__ void k_concat(const float* __restrict__ ue, const float* __restrict__ ie) {
    int i = blockIdx.x * blockDim.x + threadIdx.x;
    if (i < N_NODESC * DIM)
        g_ego[i] = (i < N_USERS * DIM) ? ue[i] : ie[i - N_USERS * DIM];
}

// ---------------- SpMM: warp per row, CSR, no atomics ----------------
// mode: 0 = write y only; 1 = y and sum = y; 2 = y and sum += y
__global__ void __launch_bounds__(256) k_spmm(int xin, int yout, int mode) {
    int w = (blockIdx.x * blockDim.x + threadIdx.x) >> 5;
    int lane = threadIdx.x & 31;
    if (w >= N_NODESC) return;
    const float* __restrict__ x = bufsel(xin);
    float* __restrict__ y = bufsel(yout);
    int s = g_rowptr[w], e = g_rowptr[w + 1];
    float a0 = 0.f, a1 = 0.f, b0 = 0.f, b1 = 0.f;
    int i = s;
    for (; i + 1 < e; i += 2) {
        int2 cv0 = g_cv[i], cv1 = g_cv[i + 1];
        const float* p0 = x + (cv0.x << 6);
        const float* p1 = x + (cv1.x << 6);
        float v0 = __int_as_float(cv0.y), v1 = __int_as_float(cv1.y);
        a0 = fmaf(v0, p0[lane], a0);      a1 = fmaf(v0, p0[lane + 32], a1);
        b0 = fmaf(v1, p1[lane], b0);      b1 = fmaf(v1, p1[lane + 32], b1);
    }
    if (i < e) {
        int2 cv = g_cv[i];
        const float* p = x + (cv.x << 6);
        float v = __int_as_float(cv.y);
        a0 = fmaf(v, p[lane], a0);        a1 = fmaf(v, p[lane + 32], a1);
    }
    a0 += b0; a1 += b1;
    int o = (w << 6) + lane;
    y[o] = a0; y[o + 32] = a1;
    if (mode == 1)      { g_sum[o] = a0;  g_sum[o + 32] = a1; }
    else if (mode == 2) { g_sum[o] += a0; g_sum[o + 32] += a1; }
}

// ---------------- noise (exact JAX uniform) + sum accumulation ----------------
// warp per row-pair (r, r+75000). Lane handles cols 2*lane, 2*lane+1.
__global__ void __launch_bounds__(256) k_noise(int ybuf, unsigned fk0, unsigned fk1, int first) {
    int w = (blockIdx.x * blockDim.x + threadIdx.x) >> 5;
    int lane = threadIdx.x & 31;
    if (w >= NPAIR) return;
    float* __restrict__ y = bufsel(ybuf);
    unsigned i0 = (unsigned)w * 64u + (unsigned)(lane * 2);
    unsigned i1 = i0 + 1u;
    unsigned a0, a1, b0, b1;
    tf2x32(fk0, fk1, i0, i0 + HALFC, a0, a1);
    tf2x32(fk0, fk1, i1, i1 + HALFC, b0, b1);
    float ur0 = u32_to_unit(a0), ur1 = u32_to_unit(b0);   // row w
    float us0 = u32_to_unit(a1), us1 = u32_to_unit(b1);   // row w + 75000
    float ssr = wredsum(ur0 * ur0 + ur1 * ur1);
    float sss = wredsum(us0 * us0 + us1 * us1);
    float scr = EPSC / sqrtf(ssr);
    float scs = EPSC / sqrtf(sss);
    int base  = w * 64 + lane * 2;
    int base2 = base + NPAIR * 64;
    float nv[4] = { ur0 * scr, ur1 * scr, us0 * scs, us1 * scs };
    int   idx[4] = { base, base + 1, base2, base2 + 1 };
#pragma unroll
    for (int t = 0; t < 4; t++) {
        float xv = y[idx[t]];
        float sg = (xv > 0.f) ? 1.f : ((xv < 0.f) ? -1.f : 0.f);
        xv += sg * nv[t];
        y[idx[t]] = xv;
        if (first) g_sum[idx[t]] = xv; else g_sum[idx[t]] += xv;
    }
}

// ---------------- BPR + reg partials (warp per batch row) ----------------
__global__ void __launch_bounds__(256) k_bpr(const int* __restrict__ ul,
                                             const int* __restrict__ pl,
                                             const int* __restrict__ nl) {
    int w = (blockIdx.x * blockDim.x + threadIdx.x) >> 5;
    int lane = threadIdx.x & 31;
    if (w >= BATCHC) return;
    const float third = 1.f / 3.f;
    int ub = ul[w] << 6;
    int pb = (N_USERS + pl[w]) << 6;
    int nb = (N_USERS + nl[w]) << 6;
    float u0 = g_sum[ub + lane] * third, u1 = g_sum[ub + lane + 32] * third;
    float p0 = g_sum[pb + lane] * third, p1 = g_sum[pb + lane + 32] * third;
    float n0 = g_sum[nb + lane] * third, n1 = g_sum[nb + lane + 32] * third;
    float pos = wredsum(u0 * p0 + u1 * p1);
    float neg = wredsum(u0 * n0 + u1 * n1);
    float ssu = wredsum(u0 * u0 + u1 * u1);
    float ssp = wredsum(p0 * p0 + p1 * p1);
    if (lane == 0) {
        float d = pos - neg;
        float sig = 1.f / (1.f + expf(-d));
        atomicAdd(&g_acc[0], -logf(1e-7f + sig));
        atomicAdd(&g_acc[1], ssu);
        atomicAdd(&g_acc[2], ssp);
    }
}

// ---------------- order-free unique ----------------
__global__ void k_unique(const int* __restrict__ list, int which) {
    int i = blockIdx.x * blockDim.x + threadIdx.x;
    if (i >= BATCHC) return;
    int v = list[i];
    int fidx = which ? (N_USERS + v) : v;
    if (atomicExch(&g_flags[fidx], 1) == 0) {
        int p = atomicAdd(which ? &g_icnt : &g_ucnt, 1);
        (which ? g_iidx : g_uidx)[p] = v;
    }
}

// ---------------- gather view rows, normalize; view 2 also computes pos ----------------
__global__ void __launch_bounds__(256) k_gatherv(int view) {
    int w = (blockIdx.x * blockDim.x + threadIdx.x) >> 5;
    int lane = threadIdx.x & 31;
    if (w >= 2 * BATCHC) return;
    int isItem = (w >= BATCHC);
    int j = isItem ? w - BATCHC : w;
    int cnt = isItem ? g_icnt : g_ucnt;
    if (j >= cnt) return;
    int row = isItem ? (N_USERS + g_iidx[j]) : g_uidx[j];
    int b = row << 6;
    float v0 = g_sum[b + lane], v1 = g_sum[b + lane + 32];
    float ss = wredsum(v0 * v0 + v1 * v1);
    float inv = 1.f / sqrtf(ss);
    v0 *= inv; v1 *= inv;
    float* dst = isItem ? (view == 1 ? g_V1i : g_V2i) : (view == 1 ? g_V1u : g_V2u);
    dst[(j << 6) + lane] = v0;
    dst[(j << 6) + lane + 32] = v1;
    if (view == 2) {
        const float* o = isItem ? g_V1i : g_V1u;
        float d = wredsum(v0 * o[(j << 6) + lane] + v1 * o[(j << 6) + lane + 32]);
        if (lane == 0) (isItem ? g_posI : g_posU)[j] = d * INV_TEMP;
    }
}

// ---------------- InfoNCE partial sums: grid (32, 16), 128 threads ----------------
#define NCE_CSPLIT 16
#define NCE_COLS (BATCHC / NCE_CSPLIT)   // 256
__global__ void __launch_bounds__(128) k_nce(int which) {
    const float* __restrict__ V1 = which ? g_V1i : g_V1u;
    const float* __restrict__ V2 = which ? g_V2i : g_V2u;
    float* __restrict__ S = g_S + which * BATCHC;
    int U = which ? g_icnt : g_ucnt;
    int r = blockIdx.x * 128 + threadIdx.x;
    float4 v[16];
    if (r < U) {
        const float4* p = (const float4*)(V1 + (r << 6));
#pragma unroll
        for (int i = 0; i < 16; i++) v[i] = p[i];
    }
    __shared__ float sh[128 * DIM];      // 32 KB tile of V2 columns
    float s = 0.f;
    int cbegin = blockIdx.y * NCE_COLS;
    for (int t = cbegin; t < cbegin + NCE_COLS; t += 128) {
        int cmax = U - t; if (cmax > 128) cmax = 128;
        if (cmax > 0) {
            const float4* src = (const float4*)(V2 + (t << 6));
            float4* d4 = (float4*)sh;
            for (int idx = threadIdx.x; idx < cmax * 16; idx += 128) d4[idx] = src[idx];
        }
        __syncthreads();
        if (r < U && cmax > 0) {
            for (int cc = 0; cc < cmax; cc++) {
                const float4* q = (const float4*)(sh + cc * DIM);
                float d0 = 0.f, d1 = 0.f, d2 = 0.f, d3 = 0.f;
#pragma unroll
                for (int i = 0; i < 16; i += 4) {
                    float4 q0 = q[i], q1 = q[i+1], q2 = q[i+2], q3 = q[i+3];
                    d0 = fmaf(v[i].x, q0.x, fmaf(v[i].y, q0.y, fmaf(v[i].z, q0.z, fmaf(v[i].w, q0.w, d0))));
                    d1 = fmaf(v[i+1].x, q1.x, fmaf(v[i+1].y, q1.y, fmaf(v[i+1].z, q1.z, fmaf(v[i+1].w, q1.w, d1))));
                    d2 = fmaf(v[i+2].x, q2.x, fmaf(v[i+2].y, q2.y, fmaf(v[i+2].z, q2.z, fmaf(v[i+2].w, q2.w, d2))));
                    d3 = fmaf(v[i+3].x, q3.x, fmaf(v[i+3].y, q3.y, fmaf(v[i+3].z, q3.z, fmaf(v[i+3].w, q3.w, d3))));
                }
                float dot = (d0 + d1) + (d2 + d3);
                s += __expf(dot * INV_TEMP - 5.0f);   // logits bounded by 5 -> fixed-max logsumexp
            }
        }
        __syncthreads();
    }
    if (r < U && s != 0.f) atomicAdd(&S[r], s);
}

__global__ void __launch_bounds__(256) k_ncefin() {
    int i = blockIdx.x * blockDim.x + threadIdx.x;
    int which = (i >= BATCHC);
    int j = i - which * BATCHC;
    int U = which ? g_icnt : g_ucnt;
    float c = 0.f;
    if (i < 2 * BATCHC && j < U)
        c = 5.0f + logf(g_S[i]) - (which ? g_posI[j] : g_posU[j]);
    c = wredsum(c);
    if ((threadIdx.x & 31) == 0 && c != 0.f)
        atomicAdd(&g_acc[3 + which], c);
}

__global__ void k_final(float* out) {
    if (threadIdx.x == 0) {
        float rec = g_acc[0] / (float)BATCHC;
        float reg = 1e-4f * (sqrtf(g_acc[1]) + sqrtf(g_acc[2]));
        float cl = 0.2f * (g_acc[3] / (float)g_ucnt + g_acc[4] / (float)g_icnt);
        out[0] = rec + reg + cl;
        out[1] = cl;
    }
}

// ---------------- launch ----------------
extern "C" void kernel_launch(void* const* d_in, const int* in_sizes, int n_in,
                              void* d_out, int out_size) {
    const float* ue = (const float*)d_in[0];
    const float* ie = (const float*)d_in[1];
    const float* av = (const float*)d_in[2];
    const int*   ar = (const int*)d_in[3];
    const int*   ac = (const int*)d_in[4];
    const int*   ul = (const int*)d_in[5];
    const int*   pl = (const int*)d_in[6];
    const int*   nl = (const int*)d_in[7];
    float* out = (float*)d_out;

    const int SCAN_BLOCKS = (N_NODESC + 1023) / 1024;   // 147
    const int SPMM_BLOCKS = (N_NODESC * 32 + 255) / 256;
    const int NOISE_BLOCKS = (NPAIR * 32 + 255) / 256;

    k_zero<<<(N_NODESC + 255) / 256, 256>>>();
    k_hist<<<(NNZC + 255) / 256, 256>>>(ar);
    k_scan1<<<SCAN_BLOCKS, 1024>>>();
    k_scan2<<<1, 32>>>(SCAN_BLOCKS);
    k_scan3<<<SCAN_BLOCKS, 1024>>>();
    k_fill<<<(NNZC + 255) / 256, 256>>>(ar, ac, av);
    k_concat<<<(N_NODESC * DIM + 255) / 256, 256>>>(ue, ie);

    // main (unperturbed) encode: sum = e1+e2+e3
    k_spmm<<<SPMM_BLOCKS, 256>>>(0, 1, 1);
    k_spmm<<<SPMM_BLOCKS, 256>>>(1, 2, 2);
    k_spmm<<<SPMM_BLOCKS, 256>>>(2, 1, 2);
    k_bpr<<<(BATCHC * 32) / 256, 256>>>(ul, pl, nl);
    k_unique<<<(BATCHC + 255) / 256, 256>>>(ul, 0);
    k_unique<<<(BATCHC + 255) / 256, 256>>>(pl, 1);

    // folded keys: fold_in(key(S), k) = threefry((0,S),(0,k))  [host-side, baked into graph]
    unsigned seeds[2] = {101u, 202u};
    unsigned fk[2][3][2];
    for (int vv = 0; vv < 2; vv++)
        for (int k = 0; k < 3; k++)
            tf2x32(0u, seeds[vv], 0u, (unsigned)k, fk[vv][k][0], fk[vv][k][1]);

    for (int vv = 0; vv < 2; vv++) {
        k_spmm<<<SPMM_BLOCKS, 256>>>(0, 1, 0);
        k_noise<<<NOISE_BLOCKS, 256>>>(1, fk[vv][0][0], fk[vv][0][1], 1);
        k_spmm<<<SPMM_BLOCKS, 256>>>(1, 2, 0);
        k_noise<<<NOISE_BLOCKS, 256>>>(2, fk[vv][1][0], fk[vv][1][1], 0);
        k_spmm<<<SPMM_BLOCKS, 256>>>(2, 1, 0);
        k_noise<<<NOISE_BLOCKS, 256>>>(1, fk[vv][2][0], fk[vv][2][1], 0);
        k_gatherv<<<(2 * BATCHC * 32) / 256, 256>>>(vv + 1);
    }

    dim3 nce_grid(BATCHC / 128, NCE_CSPLIT);
    k_nce<<<nce_grid, 128>>>(0);
    k_nce<<<nce_grid, 128>>>(1);
    k_ncefin<<<(2 * BATCHC + 255) / 256, 256>>>();
    k_final<<<1, 32>>>(out);
}

// round 2
// speedup vs baseline: 1.4560x; 1.4560x over previous
#include <cuda_runtime.h>
#include <cstdint>

#define N_USERS 100000
#define N_ITEMS 50000
#define N_NODESC 150000
#define NNZC 2400000
#define DIM 64
#define BATCHC 4096
#define HALFC 4800000u
#define NPAIR 75000
#define EPSC 0.1f
#define INV_TEMP 5.0f

// ---------------- static device scratch (allocation-free) ----------------
__device__ float g_ego [N_NODESC * DIM];
__device__ float g_e1  [N_NODESC * DIM];
__device__ float g_e2  [N_NODESC * DIM];
__device__ float g_y1v1[N_NODESC * DIM];
__device__ float g_y1v2[N_NODESC * DIM];
__device__ float g_y2v1[N_NODESC * DIM];
__device__ float g_y2v2[N_NODESC * DIM];
__device__ int2  g_cv[NNZC];            // (col, val bits) sorted by row
__device__ int   g_rowptr[N_NODESC + 1];
__device__ int   g_cursor[N_NODESC];
__device__ int   g_counts[N_NODESC];
__device__ int   g_blocksums[256];
__device__ int   g_flags[N_NODESC];
__device__ int   g_uidx[BATCHC];
__device__ int   g_iidx[BATCHC];
__device__ int   g_ucnt;
__device__ int   g_icnt;
__device__ float g_V1u[BATCHC * DIM], g_V2u[BATCHC * DIM];
__device__ float g_V1i[BATCHC * DIM], g_V2i[BATCHC * DIM];
__device__ float g_posU[BATCHC], g_posI[BATCHC];
__device__ float g_S[2 * BATCHC];
__device__ float g_acc[8];              // 0 rec, 1 ssu, 2 ssp, 3 nceU, 4 nceI

// ---------------- threefry-2x32 (exact JAX schedule) ----------------
__host__ __device__ __forceinline__ unsigned rl32(unsigned x, int r) {
    return (x << r) | (x >> (32 - r));
}
__host__ __device__ __forceinline__ void tf2x32(unsigned k0, unsigned k1,
                                                unsigned x0, unsigned x1,
                                                unsigned& o0, unsigned& o1) {
    unsigned k2 = k0 ^ k1 ^ 0x1BD11BDAu;
    x0 += k0; x1 += k1;
#define TFR(r) { x0 += x1; x1 = rl32(x1, r); x1 ^= x0; }
    TFR(13) TFR(15) TFR(26) TFR(6)
    x0 += k1; x1 += k2 + 1u;
    TFR(17) TFR(29) TFR(16) TFR(24)
    x0 += k2; x1 += k0 + 2u;
    TFR(13) TFR(15) TFR(26) TFR(6)
    x0 += k0; x1 += k1 + 3u;
    TFR(17) TFR(29) TFR(16) TFR(24)
    x0 += k1; x1 += k2 + 4u;
    TFR(13) TFR(15) TFR(26) TFR(6)
    x0 += k2; x1 += k0 + 5u;
#undef TFR
    o0 = x0; o1 = x1;
}
__device__ __forceinline__ float u32_to_unit(unsigned b) {
    return __uint_as_float((b >> 9) | 0x3f800000u) - 1.0f;
}
__device__ __forceinline__ float wredsum(float v) {
#pragma unroll
    for (int o = 16; o; o >>= 1) v += __shfl_xor_sync(0xffffffffu, v, o);
    return v;
}
__device__ __forceinline__ float sgn(float x) {
    return (x > 0.f) ? 1.f : ((x < 0.f) ? -1.f : 0.f);
}
__device__ __forceinline__ float* bufsel(int id) {
    switch (id) {
        case 0: return g_ego;
        case 1: return g_e1;
        case 2: return g_e2;
        case 3: return g_y1v1;
        case 4: return g_y1v2;
        case 5: return g_y2v1;
        default: return g_y2v2;
    }
}
// warp computes one CSR row into per-lane float2 at cols (2*lane, 2*lane+1)
__device__ __forceinline__ float2 csr_row(const float* __restrict__ x, int row, int lane) {
    int s = g_rowptr[row], e = g_rowptr[row + 1];
    float ax = 0.f, ay = 0.f, bx = 0.f, by = 0.f;
    int i = s;
    for (; i + 1 < e; i += 2) {
        int2 c0 = g_cv[i], c1 = g_cv[i + 1];
        float2 p0 = ((const float2*)(x + (c0.x << 6)))[lane];
        float2 p1 = ((const float2*)(x + (c1.x << 6)))[lane];
        float v0 = __int_as_float(c0.y), v1 = __int_as_float(c1.y);
        ax = fmaf(v0, p0.x, ax); ay = fmaf(v0, p0.y, ay);
        bx = fmaf(v1, p1.x, bx); by = fmaf(v1, p1.y, by);
    }
    if (i < e) {
        int2 c0 = g_cv[i];
        float2 p0 = ((const float2*)(x + (c0.x << 6)))[lane];
        float v0 = __int_as_float(c0.y);
        ax = fmaf(v0, p0.x, ax); ay = fmaf(v0, p0.y, ay);
    }
    return make_float2(ax + bx, ay + by);
}

// ---------------- setup ----------------
__global__ void k_init(const float* __restrict__ ue, const float* __restrict__ ie) {
    int i = blockIdx.x * blockDim.x + threadIdx.x;
    if (i < N_NODESC * DIM)
        g_ego[i] = (i < N_USERS * DIM) ? ue[i] : ie[i - N_USERS * DIM];
    if (i < N_NODESC) { g_flags[i] = 0; g_counts[i] = 0; }
    if (i < 2 * BATCHC) g_S[i] = 0.f;
    if (i < 8) g_acc[i] = 0.f;
    if (i == 0) { g_ucnt = 0; g_icnt = 0; }
}
__global__ void k_hist(const int* __restrict__ rows) {
    int i = blockIdx.x * blockDim.x + threadIdx.x;
    if (i < NNZC) atomicAdd(&g_counts[rows[i]], 1);
}
__global__ void k_scan1() {
    __shared__ int sh[1024];
    int g = blockIdx.x * 1024 + threadIdx.x;
    int v = (g < N_NODESC) ? g_counts[g] : 0;
    sh[threadIdx.x] = v;
    __syncthreads();
    for (int off = 1; off < 1024; off <<= 1) {
        int t = (threadIdx.x >= off) ? sh[threadIdx.x - off] : 0;
        __syncthreads();
        sh[threadIdx.x] += t;
        __syncthreads();
    }
    if (g < N_NODESC) g_rowptr[g] = sh[threadIdx.x] - v;
    if (threadIdx.x == 1023) g_blocksums[blockIdx.x] = sh[1023];
}
__global__ void k_scan2(int nblocks) {
    if (threadIdx.x == 0) {
        int acc = 0;
        for (int b = 0; b < nblocks; b++) { int t = g_blocksums[b]; g_blocksums[b] = acc; acc += t; }
        g_rowptr[N_NODESC] = acc;
    }
}
__global__ void k_scan3() {
    int g = blockIdx.x * blockDim.x + threadIdx.x;
    if (g < N_NODESC) {
        int v = g_rowptr[g] + g_blocksums[g >> 10];
        g_rowptr[g] = v;
        g_cursor[g] = v;
    }
}
__global__ void k_fill(const int* __restrict__ rows, const int* __restrict__ cols,
                       const float* __restrict__ vals) {
    int i = blockIdx.x * blockDim.x + threadIdx.x;
    if (i < NNZC) {
        int p = atomicAdd(&g_cursor[rows[i]], 1);
        g_cv[p] = make_int2(cols[i], __float_as_int(vals[i]));
    }
}

// ---------------- full SpMM (plain): warp per row ----------------
__global__ void __launch_bounds__(256) k_spmm(int xin, int yout) {
    int w = (blockIdx.x * blockDim.x + threadIdx.x) >> 5;
    int lane = threadIdx.x & 31;
    if (w >= N_NODESC) return;
    const float* __restrict__ x = bufsel(xin);
    float* __restrict__ y = bufsel(yout);
    float2 a = csr_row(x, w, lane);
    ((float2*)(y + (w << 6)))[lane] = a;
}

// ---------------- layer-1 noise for BOTH views (reads e1 once) ----------------
__global__ void __launch_bounds__(256) k_noise1(unsigned f10, unsigned f11,
                                                unsigned f20, unsigned f21) {
    int w = (blockIdx.x * blockDim.x + threadIdx.x) >> 5;
    int lane = threadIdx.x & 31;
    if (w >= NPAIR) return;
    int r1 = w, r2 = w + NPAIR;
    float2 ea = ((const float2*)(g_e1 + (r1 << 6)))[lane];
    float2 eb = ((const float2*)(g_e1 + (r2 << 6)))[lane];
    unsigned i0 = (unsigned)w * 64u + (unsigned)(lane * 2);
    unsigned i1 = i0 + 1u;
#pragma unroll
    for (int vv = 0; vv < 2; vv++) {
        unsigned k0 = vv ? f20 : f10, k1 = vv ? f21 : f11;
        unsigned a0, a1, b0, b1;
        tf2x32(k0, k1, i0, i0 + HALFC, a0, a1);
        tf2x32(k0, k1, i1, i1 + HALFC, b0, b1);
        float n1x = u32_to_unit(a0), n1y = u32_to_unit(b0);   // row r1
        float n2x = u32_to_unit(a1), n2y = u32_to_unit(b1);   // row r2
        float s1 = EPSC * rsqrtf(wredsum(n1x * n1x + n1y * n1y));
        float s2 = EPSC * rsqrtf(wredsum(n2x * n2x + n2y * n2y));
        float2 o1 = make_float2(ea.x + sgn(ea.x) * n1x * s1, ea.y + sgn(ea.y) * n1y * s1);
        float2 o2 = make_float2(eb.x + sgn(eb.x) * n2x * s2, eb.y + sgn(eb.y) * n2y * s2);
        float* y = vv ? g_y1v2 : g_y1v1;
        ((float2*)(y + (r1 << 6)))[lane] = o1;
        ((float2*)(y + (r2 << 6)))[lane] = o2;
    }
}

// ---------------- layer-2 SpMM with fused noise: warp per row-pair ----------------
__global__ void __launch_bounds__(256) k_spmm_noise(int xin, int yout,
                                                    unsigned fk0, unsigned fk1) {
    int w = (blockIdx.x * blockDim.x + threadIdx.x) >> 5;
    int lane = threadIdx.x & 31;
    if (w >= NPAIR) return;
    const float* __restrict__ x = bufsel(xin);
    float* __restrict__ y = bufsel(yout);
    int r1 = w, r2 = w + NPAIR;
    unsigned i0 = (unsigned)w * 64u + (unsigned)(lane * 2);
    unsigned i1 = i0 + 1u;
    unsigned a0, a1, b0, b1;
    tf2x32(fk0, fk1, i0, i0 + HALFC, a0, a1);
    tf2x32(fk0, fk1, i1, i1 + HALFC, b0, b1);
    float n1x = u32_to_unit(a0), n1y = u32_to_unit(b0);
    float n2x = u32_to_unit(a1), n2y = u32_to_unit(b1);
    float s1 = EPSC * rsqrtf(wredsum(n1x * n1x + n1y * n1y));
    float s2 = EPSC * rsqrtf(wredsum(n2x * n2x + n2y * n2y));
    float2 acc1 = csr_row(x, r1, lane);
    acc1.x += sgn(acc1.x) * n1x * s1;
    acc1.y += sgn(acc1.y) * n1y * s1;
    ((float2*)(y + (r1 << 6)))[lane] = acc1;
    float2 acc2 = csr_row(x, r2, lane);
    acc2.x += sgn(acc2.x) * n2x * s2;
    acc2.y += sgn(acc2.y) * n2y * s2;
    ((float2*)(y + (r2 << 6)))[lane] = acc2;
}

// ---------------- BPR: warp per batch entry, computes e3 rows on the fly ----------------
__global__ void __launch_bounds__(256) k_bpr(const int* __restrict__ ul,
                                             const int* __restrict__ pl,
                                             const int* __restrict__ nl) {
    int w = (blockIdx.x * blockDim.x + threadIdx.x) >> 5;
    int lane = threadIdx.x & 31;
    if (w >= BATCHC) return;
    const float third = 1.f / 3.f;
    int ru = ul[w];
    int rp = N_USERS + pl[w];
    int rn = N_USERS + nl[w];
    float2 u3 = csr_row(g_e2, ru, lane);
    float2 p3 = csr_row(g_e2, rp, lane);
    float2 n3 = csr_row(g_e2, rn, lane);
    float2 u1 = ((const float2*)(g_e1 + (ru << 6)))[lane];
    float2 u2 = ((const float2*)(g_e2 + (ru << 6)))[lane];
    float2 p1 = ((const float2*)(g_e1 + (rp << 6)))[lane];
    float2 p2 = ((const float2*)(g_e2 + (rp << 6)))[lane];
    float2 n1 = ((const float2*)(g_e1 + (rn << 6)))[lane];
    float2 n2 = ((const float2*)(g_e2 + (rn << 6)))[lane];
    float ux = (u1.x + u2.x + u3.x) * third, uy = (u1.y + u2.y + u3.y) * third;
    float px = (p1.x + p2.x + p3.x) * third, py = (p1.y + p2.y + p3.y) * third;
    float nx = (n1.x + n2.x + n3.x) * third, ny = (n1.y + n2.y + n3.y) * third;
    float pos = wredsum(ux * px + uy * py);
    float neg = wredsum(ux * nx + uy * ny);
    float ssu = wredsum(ux * ux + uy * uy);
    float ssp = wredsum(px * px + py * py);
    if (lane == 0) {
        float d = pos - neg;
        float sig = 1.f / (1.f + expf(-d));
        atomicAdd(&g_acc[0], -logf(1e-7f + sig));
        atomicAdd(&g_acc[1], ssu);
        atomicAdd(&g_acc[2], ssp);
    }
}

// ---------------- order-free unique ----------------
__global__ void k_unique(const int* __restrict__ list, int which) {
    int i = blockIdx.x * blockDim.x + threadIdx.x;
    if (i >= BATCHC) return;
    int v = list[i];
    int fidx = which ? (N_USERS + v) : v;
    if (atomicExch(&g_flags[fidx], 1) == 0) {
        int p = atomicAdd(which ? &g_icnt : &g_ucnt, 1);
        (which ? g_iidx : g_uidx)[p] = v;
    }
}

// ---------------- view finalize: layer-3 row on the fly + noise + normalize ----------------
__global__ void __launch_bounds__(256) k_vfinal(int view, unsigned fk0, unsigned fk1) {
    int w = (blockIdx.x * blockDim.x + threadIdx.x) >> 5;
    int lane = threadIdx.x & 31;
    if (w >= 2 * BATCHC) return;
    int isItem = (w >= BATCHC);
    int j = isItem ? w - BATCHC : w;
    int cnt = isItem ? g_icnt : g_ucnt;
    if (j >= cnt) return;
    int row = isItem ? (N_USERS + g_iidx[j]) : g_uidx[j];
    const float* __restrict__ y1 = (view == 1) ? g_y1v1 : g_y1v2;
    const float* __restrict__ y2 = (view == 1) ? g_y2v1 : g_y2v2;
    // layer-3 CSR row
    float2 a3 = csr_row(y2, row, lane);
    // noise3 for this single row
    int half = (row >= NPAIR);
    unsigned base = (unsigned)(half ? row - NPAIR : row) * 64u + (unsigned)(lane * 2);
    unsigned a0, a1, b0, b1;
    tf2x32(fk0, fk1, base, base + HALFC, a0, a1);
    tf2x32(fk0, fk1, base + 1u, base + 1u + HALFC, b0, b1);
    float nx = u32_to_unit(half ? a1 : a0);
    float ny = u32_to_unit(half ? b1 : b0);
    float sc = EPSC * rsqrtf(wredsum(nx * nx + ny * ny));
    a3.x += sgn(a3.x) * nx * sc;
    a3.y += sgn(a3.y) * ny * sc;
    float2 v1 = ((const float2*)(y1 + (row << 6)))[lane];
    float2 v2 = ((const float2*)(y2 + (row << 6)))[lane];
    float sx = v1.x + v2.x + a3.x;
    float sy = v1.y + v2.y + a3.y;
    float inv = rsqrtf(wredsum(sx * sx + sy * sy));
    sx *= inv; sy *= inv;
    float* dst = isItem ? (view == 1 ? g_V1i : g_V2i) : (view == 1 ? g_V1u : g_V2u);
    ((float2*)(dst + (j << 6)))[lane] = make_float2(sx, sy);
    if (view == 2) {
        const float* o = isItem ? g_V1i : g_V1u;
        float2 ov = ((const float2*)(o + (j << 6)))[lane];
        float d = wredsum(sx * ov.x + sy * ov.y);
        if (lane == 0) (isItem ? g_posI : g_posU)[j] = d * INV_TEMP;
    }
}

// ---------------- InfoNCE ----------------
#define NCE_CSPLIT 16
#define NCE_COLS (BATCHC / NCE_CSPLIT)
__global__ void __launch_bounds__(128) k_nce(int which) {
    const float* __restrict__ V1 = which ? g_V1i : g_V1u;
    const float* __restrict__ V2 = which ? g_V2i : g_V2u;
    float* __restrict__ S = g_S + which * BATCHC;
    int U = which ? g_icnt : g_ucnt;
    int r = blockIdx.x * 128 + threadIdx.x;
    float4 v[16];
    if (r < U) {
        const float4* p = (const float4*)(V1 + (r << 6));
#pragma unroll
        for (int i = 0; i < 16; i++) v[i] = p[i];
    }
    __shared__ float sh[128 * DIM];
    float s = 0.f;
    int cbegin = blockIdx.y * NCE_COLS;
    for (int t = cbegin; t < cbegin + NCE_COLS; t += 128) {
        int cmax = U - t; if (cmax > 128) cmax = 128;
        if (cmax > 0) {
            const float4* src = (const float4*)(V2 + (t << 6));
            float4* d4 = (float4*)sh;
            for (int idx = threadIdx.x; idx < cmax * 16; idx += 128) d4[idx] = src[idx];
        }
        __syncthreads();
        if (r < U && cmax > 0) {
            for (int cc = 0; cc < cmax; cc++) {
                const float4* q = (const float4*)(sh + cc * DIM);
                float d0 = 0.f, d1 = 0.f, d2 = 0.f, d3 = 0.f;
#pragma unroll
                for (int i = 0; i < 16; i += 4) {
                    float4 q0 = q[i], q1 = q[i+1], q2 = q[i+2], q3 = q[i+3];
                    d0 = fmaf(v[i].x, q0.x, fmaf(v[i].y, q0.y, fmaf(v[i].z, q0.z, fmaf(v[i].w, q0.w, d0))));
                    d1 = fmaf(v[i+1].x, q1.x, fmaf(v[i+1].y, q1.y, fmaf(v[i+1].z, q1.z, fmaf(v[i+1].w, q1.w, d1))));
                    d2 = fmaf(v[i+2].x, q2.x, fmaf(v[i+2].y, q2.y, fmaf(v[i+2].z, q2.z, fmaf(v[i+2].w, q2.w, d2))));
                    d3 = fmaf(v[i+3].x, q3.x, fmaf(v[i+3].y, q3.y, fmaf(v[i+3].z, q3.z, fmaf(v[i+3].w, q3.w, d3))));
                }
                float dot = (d0 + d1) + (d2 + d3);
                s += __expf(dot * INV_TEMP - 5.0f);
            }
        }
        __syncthreads();
    }
    if (r < U && s != 0.f) atomicAdd(&S[r], s);
}

__global__ void __launch_bounds__(256) k_ncefin() {
    int i = blockIdx.x * blockDim.x + threadIdx.x;
    int which = (i >= BATCHC);
    int j = i - which * BATCHC;
    int U = which ? g_icnt : g_ucnt;
    float c = 0.f;
    if (i < 2 * BATCHC && j < U)
        c = 5.0f + logf(g_S[i]) - (which ? g_posI[j] : g_posU[j]);
    c = wredsum(c);
    if ((threadIdx.x & 31) == 0 && c != 0.f)
        atomicAdd(&g_acc[3 + which], c);
}

__global__ void k_final(float* out) {
    if (threadIdx.x == 0) {
        float rec = g_acc[0] / (float)BATCHC;
        float reg = 1e-4f * (sqrtf(g_acc[1]) + sqrtf(g_acc[2]));
        float cl = 0.2f * (g_acc[3] / (float)g_ucnt + g_acc[4] / (float)g_icnt);
        out[0] = rec + reg + cl;
        out[1] = cl;
    }
}

// ---------------- launch ----------------
extern "C" void kernel_launch(void* const* d_in, const int* in_sizes, int n_in,
                              void* d_out, int out_size) {
    const float* ue = (const float*)d_in[0];
    const float* ie = (const float*)d_in[1];
    const float* av = (const float*)d_in[2];
    const int*   ar = (const int*)d_in[3];
    const int*   ac = (const int*)d_in[4];
    const int*   ul = (const int*)d_in[5];
    const int*   pl = (const int*)d_in[6];
    const int*   nl = (const int*)d_in[7];
    float* out = (float*)d_out;

    const int SCAN_BLOCKS = (N_NODESC + 1023) / 1024;
    const int SPMM_BLOCKS = (N_NODESC * 32 + 255) / 256;
    const int PAIR_BLOCKS = (NPAIR * 32 + 255) / 256;

    // folded keys: fold_in(key(S), k) = threefry((0,S),(0,k))
    unsigned seeds[2] = {101u, 202u};
    unsigned fk[2][3][2];
    for (int vv = 0; vv < 2; vv++)
        for (int k = 0; k < 3; k++)
            tf2x32(0u, seeds[vv], 0u, (unsigned)k, fk[vv][k][0], fk[vv][k][1]);

    k_init<<<(N_NODESC * DIM + 255) / 256, 256>>>(ue, ie);
    k_hist<<<(NNZC + 255) / 256, 256>>>(ar);
    k_scan1<<<SCAN_BLOCKS, 1024>>>();
    k_scan2<<<1, 32>>>(SCAN_BLOCKS);
    k_scan3<<<SCAN_BLOCKS, 1024>>>();
    k_fill<<<(NNZC + 255) / 256, 256>>>(ar, ac, av);

    // shared layer-1 and layer-2 of main encode
    k_spmm<<<SPMM_BLOCKS, 256>>>(0, 1);   // e1 = A * ego
    k_spmm<<<SPMM_BLOCKS, 256>>>(1, 2);   // e2 = A * e1
    k_bpr<<<(BATCHC * 32) / 256, 256>>>(ul, pl, nl);   // e3 rows on the fly
    k_unique<<<(BATCHC + 255) / 256, 256>>>(ul, 0);
    k_unique<<<(BATCHC + 255) / 256, 256>>>(pl, 1);

    // views: layer-1 noise (shared e1), fused layer-2, tiny layer-3 in vfinal
    k_noise1<<<PAIR_BLOCKS, 256>>>(fk[0][0][0], fk[0][0][1], fk[1][0][0], fk[1][0][1]);
    k_spmm_noise<<<PAIR_BLOCKS, 256>>>(3, 5, fk[0][1][0], fk[0][1][1]);  // v1: y2 = A*y1 + n2
    k_spmm_noise<<<PAIR_BLOCKS, 256>>>(4, 6, fk[1][1][0], fk[1][1][1]);  // v2
    k_vfinal<<<(2 * BATCHC * 32) / 256, 256>>>(1, fk[0][2][0], fk[0][2][1]);
    k_vfinal<<<(2 * BATCHC * 32) / 256, 256>>>(2, fk[1][2][0], fk[1][2][1]);

    dim3 nce_grid(BATCHC / 128, NCE_CSPLIT);
    k_nce<<<nce_grid, 128>>>(0);
    k_nce<<<nce_grid, 128>>>(1);
    k_ncefin<<<(2 * BATCHC + 255) / 256, 256>>>();
    k_final<<<1, 32>>>(out);
}

// round 5
// speedup vs baseline: 1.6451x; 1.1298x over previous
#include <cuda_runtime.h>
#include <cstdint>

#define N_USERS 100000
#define N_ITEMS 50000
#define N_NODESC 150000
#define NNZC 2400000
#define DIM 64
#define BATCHC 4096
#define HALFC 4800000u
#define NPAIR 75000
#define EPSC 0.1f
#define INV_TEMP 5.0f

// ---------------- static device scratch (allocation-free) ----------------
__device__ float  g_ego[N_NODESC * DIM];
__device__ float  g_e1 [N_NODESC * DIM];
__device__ float  g_e2 [N_NODESC * DIM];
__device__ float4 g_y1 [N_NODESC * 32];   // interleaved: (v1x,v1y,v2x,v2y) at [row*32+lane]
__device__ float4 g_y2 [N_NODESC * 32];
__device__ int2   g_cv[NNZC];
__device__ int    g_rowptr[N_NODESC + 1];
__device__ int    g_cursor[N_NODESC];
__device__ int    g_counts[N_NODESC];
__device__ int    g_blocksums[256];
__device__ int    g_flags[N_NODESC];
__device__ int    g_uidx[BATCHC];
__device__ int    g_iidx[BATCHC];
__device__ int    g_ucnt;
__device__ int    g_icnt;
__device__ float  g_V1u[BATCHC * DIM], g_V2u[BATCHC * DIM];
__device__ float  g_V1i[BATCHC * DIM], g_V2i[BATCHC * DIM];
__device__ float  g_posU[BATCHC], g_posI[BATCHC];
__device__ float  g_S[2 * BATCHC];
__device__ float  g_acc[8];               // 0 rec, 1 ssu, 2 ssp, 3 nceU, 4 nceI

// ---------------- threefry-2x32 (exact JAX schedule) ----------------
__host__ __device__ __forceinline__ unsigned rl32(unsigned x, int r) {
    return (x << r) | (x >> (32 - r));
}
__host__ __device__ __forceinline__ void tf2x32(unsigned k0, unsigned k1,
                                                unsigned x0, unsigned x1,
                                                unsigned& o0, unsigned& o1) {
    unsigned k2 = k0 ^ k1 ^ 0x1BD11BDAu;
    x0 += k0; x1 += k1;
#define TFR(r) { x0 += x1; x1 = rl32(x1, r); x1 ^= x0; }
    TFR(13) TFR(15) TFR(26) TFR(6)
    x0 += k1; x1 += k2 + 1u;
    TFR(17) TFR(29) TFR(16) TFR(24)
    x0 += k2; x1 += k0 + 2u;
    TFR(13) TFR(15) TFR(26) TFR(6)
    x0 += k0; x1 += k1 + 3u;
    TFR(17) TFR(29) TFR(16) TFR(24)
    x0 += k1; x1 += k2 + 4u;
    TFR(13) TFR(15) TFR(26) TFR(6)
    x0 += k2; x1 += k0 + 5u;
#undef TFR
    o0 = x0; o1 = x1;
}
__device__ __forceinline__ float u32_to_unit(unsigned b) {
    return __uint_as_float((b >> 9) | 0x3f800000u) - 1.0f;
}
__device__ __forceinline__ float wredsum(float v) {
#pragma unroll
    for (int o = 16; o; o >>= 1) v += __shfl_xor_sync(0xffffffffu, v, o);
    return v;
}
__device__ __forceinline__ float sgn(float x) {
    return (x > 0.f) ? 1.f : ((x < 0.f) ? -1.f : 0.f);
}

// warp computes one CSR row (float2 source) at cols (2*lane, 2*lane+1); 4-wide MLP
__device__ __forceinline__ float2 csr_row(const float* __restrict__ x, int row, int lane) {
    int s = g_rowptr[row], e = g_rowptr[row + 1];
    float ax = 0.f, ay = 0.f, bx = 0.f, by = 0.f;
    float cx = 0.f, cy = 0.f, dx = 0.f, dy = 0.f;
    int i = s;
    for (; i + 3 < e; i += 4) {
        int2 c0 = g_cv[i], c1 = g_cv[i + 1], c2 = g_cv[i + 2], c3 = g_cv[i + 3];
        float2 p0 = ((const float2*)(x + (c0.x << 6)))[lane];
        float2 p1 = ((const float2*)(x + (c1.x << 6)))[lane];
        float2 p2 = ((const float2*)(x + (c2.x << 6)))[lane];
        float2 p3 = ((const float2*)(x + (c3.x << 6)))[lane];
        float v0 = __int_as_float(c0.y), v1 = __int_as_float(c1.y);
        float v2 = __int_as_float(c2.y), v3 = __int_as_float(c3.y);
        ax = fmaf(v0, p0.x, ax); ay = fmaf(v0, p0.y, ay);
        bx = fmaf(v1, p1.x, bx); by = fmaf(v1, p1.y, by);
        cx = fmaf(v2, p2.x, cx); cy = fmaf(v2, p2.y, cy);
        dx = fmaf(v3, p3.x, dx); dy = fmaf(v3, p3.y, dy);
    }
    if (i + 1 < e) {
        int2 c0 = g_cv[i], c1 = g_cv[i + 1];
        float2 p0 = ((const float2*)(x + (c0.x << 6)))[lane];
        float2 p1 = ((const float2*)(x + (c1.x << 6)))[lane];
        float v0 = __int_as_float(c0.y), v1 = __int_as_float(c1.y);
        ax = fmaf(v0, p0.x, ax); ay = fmaf(v0, p0.y, ay);
        bx = fmaf(v1, p1.x, bx); by = fmaf(v1, p1.y, by);
        i += 2;
    }
    if (i < e) {
        int2 c0 = g_cv[i];
        float2 p0 = ((const float2*)(x + (c0.x << 6)))[lane];
        float v0 = __int_as_float(c0.y);
        cx = fmaf(v0, p0.x, cx); cy = fmaf(v0, p0.y, cy);
    }
    return make_float2((ax + bx) + (cx + dx), (ay + by) + (cy + dy));
}

// warp computes one CSR row over interleaved float4 source (both views); 4-wide MLP
__device__ __forceinline__ float4 csr_row4(const float4* __restrict__ x, int row, int lane) {
    int s = g_rowptr[row], e = g_rowptr[row + 1];
    float ax = 0.f, ay = 0.f, az = 0.f, aw = 0.f;
    float bx = 0.f, by = 0.f, bz = 0.f, bw = 0.f;
    float cx2 = 0.f, cy2 = 0.f, cz2 = 0.f, cw2 = 0.f;
    float dx2 = 0.f, dy2 = 0.f, dz2 = 0.f, dw2 = 0.f;
    int i = s;
    for (; i + 3 < e; i += 4) {
        int2 c0 = g_cv[i], c1 = g_cv[i + 1], c2 = g_cv[i + 2], c3 = g_cv[i + 3];
        float4 p0 = x[(c0.x << 5) + lane];
        float4 p1 = x[(c1.x << 5) + lane];
        float4 p2 = x[(c2.x << 5) + lane];
        float4 p3 = x[(c3.x << 5) + lane];
        float v0 = __int_as_float(c0.y), v1 = __int_as_float(c1.y);
        float v2 = __int_as_float(c2.y), v3 = __int_as_float(c3.y);
        ax = fmaf(v0, p0.x, ax); ay = fmaf(v0, p0.y, ay);
        az = fmaf(v0, p0.z, az); aw = fmaf(v0, p0.w, aw);
        bx = fmaf(v1, p1.x, bx); by = fmaf(v1, p1.y, by);
        bz = fmaf(v1, p1.z, bz); bw = fmaf(v1, p1.w, bw);
        cx2 = fmaf(v2, p2.x, cx2); cy2 = fmaf(v2, p2.y, cy2);
        cz2 = fmaf(v2, p2.z, cz2); cw2 = fmaf(v2, p2.w, cw2);
        dx2 = fmaf(v3, p3.x, dx2); dy2 = fmaf(v3, p3.y, dy2);
        dz2 = fmaf(v3, p3.z, dz2); dw2 = fmaf(v3, p3.w, dw2);
    }
    for (; i < e; i++) {
        int2 c0 = g_cv[i];
        float4 p0 = x[(c0.x << 5) + lane];
        float v0 = __int_as_float(c0.y);
        ax = fmaf(v0, p0.x, ax); ay = fmaf(v0, p0.y, ay);
        az = fmaf(v0, p0.z, az); aw = fmaf(v0, p0.w, aw);
    }
    return make_float4((ax + bx) + (cx2 + dx2), (ay + by) + (cy2 + dy2),
                       (az + bz) + (cz2 + dz2), (aw + bw) + (cw2 + dw2));
}

// ---------------- setup ----------------
__global__ void k_init(const float* __restrict__ ue, const float* __restrict__ ie) {
    int i = blockIdx.x * blockDim.x + threadIdx.x;
    if (i < N_NODESC * DIM)
        g_ego[i] = (i < N_USERS * DIM) ? ue[i] : ie[i - N_USERS * DIM];
    if (i < N_NODESC) { g_flags[i] = 0; g_counts[i] = 0; }
    if (i < 2 * BATCHC) g_S[i] = 0.f;
    if (i < 8) g_acc[i] = 0.f;
    if (i == 0) { g_ucnt = 0; g_icnt = 0; }
}
__global__ void k_hist(const int* __restrict__ rows) {
    int i = blockIdx.x * blockDim.x + threadIdx.x;
    if (i < NNZC) atomicAdd(&g_counts[rows[i]], 1);
}
__global__ void k_scan1() {
    __shared__ int sh[1024];
    int g = blockIdx.x * 1024 + threadIdx.x;
    int v = (g < N_NODESC) ? g_counts[g] : 0;
    sh[threadIdx.x] = v;
    __syncthreads();
    for (int off = 1; off < 1024; off <<= 1) {
        int t = (threadIdx.x >= off) ? sh[threadIdx.x - off] : 0;
        __syncthreads();
        sh[threadIdx.x] += t;
        __syncthreads();
    }
    if (g < N_NODESC) g_rowptr[g] = sh[threadIdx.x] - v;
    if (threadIdx.x == 1023) g_blocksums[blockIdx.x] = sh[1023];
}
// serial scan of 147 block sums (proven-stable R2 version; 7us, off critical path)
__global__ void k_scan2(int nblocks) {
    if (threadIdx.x == 0) {
        int acc = 0;
        for (int b = 0; b < nblocks; b++) { int t = g_blocksums[b]; g_blocksums[b] = acc; acc += t; }
        g_rowptr[N_NODESC] = acc;
    }
}
__global__ void k_scan3() {
    int g = blockIdx.x * blockDim.x + threadIdx.x;
    if (g < N_NODESC) {
        int v = g_rowptr[g] + g_blocksums[g >> 10];
        g_rowptr[g] = v;
        g_cursor[g] = v;
    }
}
__global__ void k_fill(const int* __restrict__ rows, const int* __restrict__ cols,
                       const float* __restrict__ vals) {
    int i = blockIdx.x * blockDim.x + threadIdx.x;
    if (i < NNZC) {
        int p = atomicAdd(&g_cursor[rows[i]], 1);
        g_cv[p] = make_int2(cols[i], __float_as_int(vals[i]));
    }
}

// ---------------- e1 = A*ego, with fused layer-1 noise for BOTH views ----------------
__global__ void __launch_bounds__(256) k_spmm_e1_noise(unsigned f10, unsigned f11,
                                                       unsigned f20, unsigned f21) {
    int w = (blockIdx.x * blockDim.x + threadIdx.x) >> 5;
    int lane = threadIdx.x & 31;
    if (w >= NPAIR) return;
    int r1 = w, r2 = w + NPAIR;
    float2 ea = csr_row(g_ego, r1, lane);
    float2 eb = csr_row(g_ego, r2, lane);
    ((float2*)(g_e1 + (r1 << 6)))[lane] = ea;
    ((float2*)(g_e1 + (r2 << 6)))[lane] = eb;
    unsigned i0 = (unsigned)w * 64u + (unsigned)(lane * 2);
    unsigned i1 = i0 + 1u;
    float4 o1, o2;
    {
        unsigned a0, a1, b0, b1;
        tf2x32(f10, f11, i0, i0 + HALFC, a0, a1);
        tf2x32(f10, f11, i1, i1 + HALFC, b0, b1);
        float n1x = u32_to_unit(a0), n1y = u32_to_unit(b0);
        float n2x = u32_to_unit(a1), n2y = u32_to_unit(b1);
        float s1 = EPSC * rsqrtf(wredsum(n1x * n1x + n1y * n1y));
        float s2 = EPSC * rsqrtf(wredsum(n2x * n2x + n2y * n2y));
        o1.x = ea.x + sgn(ea.x) * n1x * s1;  o1.y = ea.y + sgn(ea.y) * n1y * s1;
        o2.x = eb.x + sgn(eb.x) * n2x * s2;  o2.y = eb.y + sgn(eb.y) * n2y * s2;
    }
    {
        unsigned a0, a1, b0, b1;
        tf2x32(f20, f21, i0, i0 + HALFC, a0, a1);
        tf2x32(f20, f21, i1, i1 + HALFC, b0, b1);
        float n1x = u32_to_unit(a0), n1y = u32_to_unit(b0);
        float n2x = u32_to_unit(a1), n2y = u32_to_unit(b1);
        float s1 = EPSC * rsqrtf(wredsum(n1x * n1x + n1y * n1y));
        float s2 = EPSC * rsqrtf(wredsum(n2x * n2x + n2y * n2y));
        o1.z = ea.x + sgn(ea.x) * n1x * s1;  o1.w = ea.y + sgn(ea.y) * n1y * s1;
        o2.z = eb.x + sgn(eb.x) * n2x * s2;  o2.w = eb.y + sgn(eb.y) * n2y * s2;
    }
    g_y1[(r1 << 5) + lane] = o1;
    g_y1[(r2 << 5) + lane] = o2;
}

// ---------------- e2 = A*e1 (plain, warp per row) ----------------
__global__ void __launch_bounds__(256) k_spmm_e2() {
    int w = (blockIdx.x * blockDim.x + threadIdx.x) >> 5;
    int lane = threadIdx.x & 31;
    if (w >= N_NODESC) return;
    float2 a = csr_row(g_e1, w, lane);
    ((float2*)(g_e2 + (w << 6)))[lane] = a;
}

// ---------------- y2 = A*y1 (both views via float4) + fused layer-2 noise ----------------
__global__ void __launch_bounds__(256) k_spmm2v(unsigned f10, unsigned f11,
                                                unsigned f20, unsigned f21) {
    int w = (blockIdx.x * blockDim.x + threadIdx.x) >> 5;
    int lane = threadIdx.x & 31;
    if (w >= NPAIR) return;
    int r1 = w, r2 = w + NPAIR;
    unsigned i0 = (unsigned)w * 64u + (unsigned)(lane * 2);
    unsigned i1 = i0 + 1u;
    float v1n1x, v1n1y, v1n2x, v1n2y, v1s1, v1s2;
    float v2n1x, v2n1y, v2n2x, v2n2y, v2s1, v2s2;
    {
        unsigned a0, a1, b0, b1;
        tf2x32(f10, f11, i0, i0 + HALFC, a0, a1);
        tf2x32(f10, f11, i1, i1 + HALFC, b0, b1);
        v1n1x = u32_to_unit(a0); v1n1y = u32_to_unit(b0);
        v1n2x = u32_to_unit(a1); v1n2y = u32_to_unit(b1);
        v1s1 = EPSC * rsqrtf(wredsum(v1n1x * v1n1x + v1n1y * v1n1y));
        v1s2 = EPSC * rsqrtf(wredsum(v1n2x * v1n2x + v1n2y * v1n2y));
    }
    {
        unsigned a0, a1, b0, b1;
        tf2x32(f20, f21, i0, i0 + HALFC, a0, a1);
        tf2x32(f20, f21, i1, i1 + HALFC, b0, b1);
        v2n1x = u32_to_unit(a0); v2n1y = u32_to_unit(b0);
        v2n2x = u32_to_unit(a1); v2n2y = u32_to_unit(b1);
        v2s1 = EPSC * rsqrtf(wredsum(v2n1x * v2n1x + v2n1y * v2n1y));
        v2s2 = EPSC * rsqrtf(wredsum(v2n2x * v2n2x + v2n2y * v2n2y));
    }
    float4 a = csr_row4(g_y1, r1, lane);
    a.x += sgn(a.x) * v1n1x * v1s1;  a.y += sgn(a.y) * v1n1y * v1s1;
    a.z += sgn(a.z) * v2n1x * v2s1;  a.w += sgn(a.w) * v2n1y * v2s1;
    g_y2[(r1 << 5) + lane] = a;
    float4 b = csr_row4(g_y1, r2, lane);
    b.x += sgn(b.x) * v1n2x * v1s2;  b.y += sgn(b.y) * v1n2y * v1s2;
    b.z += sgn(b.z) * v2n2x * v2s2;  b.w += sgn(b.w) * v2n2y * v2s2;
    g_y2[(r2 << 5) + lane] = b;
}

// ---------------- BPR: warp per batch entry, layer-3 rows on the fly ----------------
__global__ void __launch_bounds__(256) k_bpr(const int* __restrict__ ul,
                                             const int* __restrict__ pl,
                                             const int* __restrict__ nl) {
    int w = (blockIdx.x * blockDim.x + threadIdx.x) >> 5;
    int lane = threadIdx.x & 31;
    if (w >= BATCHC) return;
    const float third = 1.f / 3.f;
    int ru = ul[w];
    int rp = N_USERS + pl[w];
    int rn = N_USERS + nl[w];
    float2 u3 = csr_row(g_e2, ru, lane);
    float2 p3 = csr_row(g_e2, rp, lane);
    float2 n3 = csr_row(g_e2, rn, lane);
    float2 u1 = ((const float2*)(g_e1 + (ru << 6)))[lane];
    float2 u2 = ((const float2*)(g_e2 + (ru << 6)))[lane];
    float2 p1 = ((const float2*)(g_e1 + (rp << 6)))[lane];
    float2 p2 = ((const float2*)(g_e2 + (rp << 6)))[lane];
    float2 n1 = ((const float2*)(g_e1 + (rn << 6)))[lane];
    float2 n2 = ((const float2*)(g_e2 + (rn << 6)))[lane];
    float ux = (u1.x + u2.x + u3.x) * third, uy = (u1.y + u2.y + u3.y) * third;
    float px = (p1.x + p2.x + p3.x) * third, py = (p1.y + p2.y + p3.y) * third;
    float nx = (n1.x + n2.x + n3.x) * third, ny = (n1.y + n2.y + n3.y) * third;
    float pos = wredsum(ux * px + uy * py);
    float neg = wredsum(ux * nx + uy * ny);
    float ssu = wredsum(ux * ux + uy * uy);
    float ssp = wredsum(px * px + py * py);
    if (lane == 0) {
        float d = pos - neg;
        float sig = 1.f / (1.f + expf(-d));
        atomicAdd(&g_acc[0], -logf(1e-7f + sig));
        atomicAdd(&g_acc[1], ssu);
        atomicAdd(&g_acc[2], ssp);
    }
}

// ---------------- order-free unique ----------------
__global__ void k_unique(const int* __restrict__ list, int which) {
    int i = blockIdx.x * blockDim.x + threadIdx.x;
    if (i >= BATCHC) return;
    int v = list[i];
    int fidx = which ? (N_USERS + v) : v;
    if (atomicExch(&g_flags[fidx], 1) == 0) {
        int p = atomicAdd(which ? &g_icnt : &g_ucnt, 1);
        (which ? g_iidx : g_uidx)[p] = v;
    }
}

// ---------------- finalize both views: layer-3 + noise + normalize + pos ----------------
__global__ void __launch_bounds__(256) k_vfinal(unsigned f10, unsigned f11,
                                                unsigned f20, unsigned f21) {
    int w = (blockIdx.x * blockDim.x + threadIdx.x) >> 5;
    int lane = threadIdx.x & 31;
    if (w >= 2 * BATCHC) return;
    int isItem = (w >= BATCHC);
    int j = isItem ? w - BATCHC : w;
    int cnt = isItem ? g_icnt : g_ucnt;
    if (j >= cnt) return;
    int row = isItem ? (N_USERS + g_iidx[j]) : g_uidx[j];
    float4 a3 = csr_row4(g_y2, row, lane);
    int half = (row >= NPAIR);
    unsigned base = (unsigned)(half ? row - NPAIR : row) * 64u + (unsigned)(lane * 2);
    {
        unsigned a0, a1, b0, b1;
        tf2x32(f10, f11, base, base + HALFC, a0, a1);
        tf2x32(f10, f11, base + 1u, base + 1u + HALFC, b0, b1);
        float nx = u32_to_unit(half ? a1 : a0);
        float ny = u32_to_unit(half ? b1 : b0);
        float sc = EPSC * rsqrtf(wredsum(nx * nx + ny * ny));
        a3.x += sgn(a3.x) * nx * sc;
        a3.y += sgn(a3.y) * ny * sc;
    }
    {
        unsigned a0, a1, b0, b1;
        tf2x32(f20, f21, base, base + HALFC, a0, a1);
        tf2x32(f20, f21, base + 1u, base + 1u + HALFC, b0, b1);
        float nx = u32_to_unit(half ? a1 : a0);
        float ny = u32_to_unit(half ? b1 : b0);
        float sc = EPSC * rsqrtf(wredsum(nx * nx + ny * ny));
        a3.z += sgn(a3.z) * nx * sc;
        a3.w += sgn(a3.w) * ny * sc;
    }
    float4 y1r = g_y1[(row << 5) + lane];
    float4 y2r = g_y2[(row << 5) + lane];
    float s1x = y1r.x + y2r.x + a3.x;
    float s1y = y1r.y + y2r.y + a3.y;
    float inv1 = rsqrtf(wredsum(s1x * s1x + s1y * s1y));
    s1x *= inv1; s1y *= inv1;
    float s2x = y1r.z + y2r.z + a3.z;
    float s2y = y1r.w + y2r.w + a3.w;
    float inv2 = rsqrtf(wredsum(s2x * s2x + s2y * s2y));
    s2x *= inv2; s2y *= inv2;
    float* d1 = isItem ? g_V1i : g_V1u;
    float* d2 = isItem ? g_V2i : g_V2u;
    ((float2*)(d1 + (j << 6)))[lane] = make_float2(s1x, s1y);
    ((float2*)(d2 + (j << 6)))[lane] = make_float2(s2x, s2y);
    float d = wredsum(s2x * s1x + s2y * s1y);
    if (lane == 0) (isItem ? g_posI : g_posU)[j] = d * INV_TEMP;
}

// ---------------- InfoNCE ----------------
#define NCE_CSPLIT 16
#define NCE_COLS (BATCHC / NCE_CSPLIT)
__global__ void __launch_bounds__(128) k_nce(int which) {
    const float* __restrict__ V1 = which ? g_V1i : g_V1u;
    const float* __restrict__ V2 = which ? g_V2i : g_V2u;
    float* __restrict__ S = g_S + which * BATCHC;
    int U = which ? g_icnt : g_ucnt;
    int r = blockIdx.x * 128 + threadIdx.x;
    float4 v[16];
    if (r < U) {
        const float4* p = (const float4*)(V1 + (r << 6));
#pragma unroll
        for (int i = 0; i < 16; i++) v[i] = p[i];
    }
    __shared__ float sh[128 * DIM];
    float s = 0.f;
    int cbegin = blockIdx.y * NCE_COLS;
    for (int t = cbegin; t < cbegin + NCE_COLS; t += 128) {
        int cmax = U - t; if (cmax > 128) cmax = 128;
        if (cmax > 0) {
            const float4* src = (const float4*)(V2 + (t << 6));
            float4* d4 = (float4*)sh;
            for (int idx = threadIdx.x; idx < cmax * 16; idx += 128) d4[idx] = src[idx];
        }
        __syncthreads();
        if (r < U && cmax > 0) {
            for (int cc = 0; cc < cmax; cc++) {
                const float4* q = (const float4*)(sh + cc * DIM);
                float d0 = 0.f, d1 = 0.f, d2 = 0.f, d3 = 0.f;
#pragma unroll
                for (int i = 0; i < 16; i += 4) {
                    float4 q0 = q[i], q1 = q[i+1], q2 = q[i+2], q3 = q[i+3];
                    d0 = fmaf(v[i].x, q0.x, fmaf(v[i].y, q0.y, fmaf(v[i].z, q0.z, fmaf(v[i].w, q0.w, d0))));
                    d1 = fmaf(v[i+1].x, q1.x, fmaf(v[i+1].y, q1.y, fmaf(v[i+1].z, q1.z, fmaf(v[i+1].w, q1.w, d1))));
                    d2 = fmaf(v[i+2].x, q2.x, fmaf(v[i+2].y, q2.y, fmaf(v[i+2].z, q2.z, fmaf(v[i+2].w, q2.w, d2))));
                    d3 = fmaf(v[i+3].x, q3.x, fmaf(v[i+3].y, q3.y, fmaf(v[i+3].z, q3.z, fmaf(v[i+3].w, q3.w, d3))));
                }
                float dot = (d0 + d1) + (d2 + d3);
                s += __expf(dot * INV_TEMP - 5.0f);
            }
        }
        __syncthreads();
    }
    if (r < U && s != 0.f) atomicAdd(&S[r], s);
}

__global__ void __launch_bounds__(256) k_ncefin() {
    int i = blockIdx.x * blockDim.x + threadIdx.x;
    int which = (i >= BATCHC);
    int j = i - which * BATCHC;
    int U = which ? g_icnt : g_ucnt;
    float c = 0.f;
    if (i < 2 * BATCHC && j < U)
        c = 5.0f + logf(g_S[i]) - (which ? g_posI[j] : g_posU[j]);
    c = wredsum(c);
    if ((threadIdx.x & 31) == 0 && c != 0.f)
        atomicAdd(&g_acc[3 + which], c);
}

__global__ void k_final(float* out) {
    if (threadIdx.x == 0) {
        float rec = g_acc[0] / (float)BATCHC;
        float reg = 1e-4f * (sqrtf(g_acc[1]) + sqrtf(g_acc[2]));
        float cl = 0.2f * (g_acc[3] / (float)g_ucnt + g_acc[4] / (float)g_icnt);
        out[0] = rec + reg + cl;
        out[1] = cl;
    }
}

// ---------------- launch ----------------
extern "C" void kernel_launch(void* const* d_in, const int* in_sizes, int n_in,
                              void* d_out, int out_size) {
    const float* ue = (const float*)d_in[0];
    const float* ie = (const float*)d_in[1];
    const float* av = (const float*)d_in[2];
    const int*   ar = (const int*)d_in[3];
    const int*   ac = (const int*)d_in[4];
    const int*   ul = (const int*)d_in[5];
    const int*   pl = (const int*)d_in[6];
    const int*   nl = (const int*)d_in[7];
    float* out = (float*)d_out;

    const int SCAN_BLOCKS = (N_NODESC + 1023) / 1024;
    const int SPMM_BLOCKS = (N_NODESC * 32 + 255) / 256;
    const int PAIR_BLOCKS = (NPAIR * 32 + 255) / 256;

    unsigned seeds[2] = {101u, 202u};
    unsigned fk[2][3][2];
    for (int vv = 0; vv < 2; vv++)
        for (int k = 0; k < 3; k++)
            tf2x32(0u, seeds[vv], 0u, (unsigned)k, fk[vv][k][0], fk[vv][k][1]);

    k_init<<<(N_NODESC * DIM + 255) / 256, 256>>>(ue, ie);
    k_hist<<<(NNZC + 255) / 256, 256>>>(ar);
    k_scan1<<<SCAN_BLOCKS, 1024>>>();
    k_scan2<<<1, 32>>>(SCAN_BLOCKS);
    k_scan3<<<SCAN_BLOCKS, 1024>>>();
    k_fill<<<(NNZC + 255) / 256, 256>>>(ar, ac, av);

    k_spmm_e1_noise<<<PAIR_BLOCKS, 256>>>(fk[0][0][0], fk[0][0][1], fk[1][0][0], fk[1][0][1]);
    k_spmm_e2<<<SPMM_BLOCKS, 256>>>();
    k_bpr<<<(BATCHC * 32) / 256, 256>>>(ul, pl, nl);
    k_unique<<<(BATCHC + 255) / 256, 256>>>(ul, 0);
    k_unique<<<(BATCHC + 255) / 256, 256>>>(pl, 1);
    k_spmm2v<<<PAIR_BLOCKS, 256>>>(fk[0][1][0], fk[0][1][1], fk[1][1][0], fk[1][1][1]);
    k_vfinal<<<(2 * BATCHC * 32) / 256, 256>>>(fk[0][2][0], fk[0][2][1], fk[1][2][0], fk[1][2][1]);

    dim3 nce_grid(BATCHC / 128, NCE_CSPLIT);
    k_nce<<<nce_grid, 128>>>(0);
    k_nce<<<nce_grid, 128>>>(1);
    k_ncefin<<<(2 * BATCHC + 255) / 256, 256>>>();
    k_final<<<1, 32>>>(out);
}